// round 10
// baseline (speedup 1.0000x reference)
#include <cuda_runtime.h>
#include <cuda_bf16.h>
#include <cstdint>

#define DINLINE __device__ __forceinline__

// ---------------------------------------------------------------------------
// helpers
// ---------------------------------------------------------------------------
DINLINE uint32_t f2tf(float x) {
    uint32_t r;
    asm("cvt.rna.tf32.f32 %0, %1;" : "=r"(r) : "f"(x));
    return r;
}

DINLINE void mma8(float c[4], const uint32_t a[4], const uint32_t b[2]) {
    asm volatile(
        "mma.sync.aligned.m16n8k8.row.col.f32.tf32.tf32.f32 "
        "{%0,%1,%2,%3}, {%4,%5,%6,%7}, {%8,%9}, {%0,%1,%2,%3};"
        : "+f"(c[0]), "+f"(c[1]), "+f"(c[2]), "+f"(c[3])
        : "r"(a[0]), "r"(a[1]), "r"(a[2]), "r"(a[3]), "r"(b[0]), "r"(b[1]));
}

DINLINE void ldsm4(uint32_t r[4], uint32_t addr) {
    asm volatile("ldmatrix.sync.aligned.m8n8.x4.shared.b16 {%0,%1,%2,%3}, [%4];"
                 : "=r"(r[0]), "=r"(r[1]), "=r"(r[2]), "=r"(r[3]) : "r"(addr));
}

DINLINE void cpa16(void* sm, const void* g) {
    uint32_t a = (uint32_t)__cvta_generic_to_shared(sm);
    asm volatile("cp.async.cg.shared.global [%0], [%1], 16;\n" :: "r"(a), "l"(g));
}
DINLINE void cpa_commit() { asm volatile("cp.async.commit_group;\n"); }
template <int N> DINLINE void cpa_wait() { asm volatile("cp.async.wait_group %0;\n" :: "n"(N)); }

DINLINE uint32_t smem_u32(const void* p) {
    uint32_t a;
    asm("{ .reg .u64 t; cvta.to.shared.u64 t, %1; cvt.u32.u64 %0, t; }"
        : "=r"(a) : "l"(p));
    return a;
}

// ---------------------------------------------------------------------------
// Scratch
// ---------------------------------------------------------------------------
__device__ float g_Q[1048576];     // tf32-rounded bits
__device__ float g_K[1048576];     // tf32-rounded bits
__device__ float g_Vt[1048576];    // [h][d][j], tf32-rounded bits
__device__ float g_G[1048576];
__device__ float g_O[1048576];     // tf32-rounded bits (gated)
__device__ __nv_bfloat16 g_Z[16777216];  // [h][i][j] bf16
__device__ float g_R[7340032];     // tf32-rounded: s, kin, Wq, Wk, Wv, Wg, Wo

// ---------------------------------------------------------------------------
// Pre-round 7 x 1M-float buffers to tf32 (rna): mainloops then need no CVT.
// ---------------------------------------------------------------------------
__global__ void round7_k(const float* __restrict__ s, const float* __restrict__ kin,
                         const float* __restrict__ Wq, const float* __restrict__ Wk,
                         const float* __restrict__ Wv, const float* __restrict__ Wg,
                         const float* __restrict__ Wo, float* __restrict__ R)
{
    long i = (long)blockIdx.x * 256 + threadIdx.x;   // float4 index
    int which = (int)(i >> 18);                      // 262144 float4 per buffer
    long off = (i & 262143) << 2;
    const float* src = which == 0 ? s : which == 1 ? kin : which == 2 ? Wq
                     : which == 3 ? Wk : which == 4 ? Wv : which == 5 ? Wg : Wo;
    float4 v = *reinterpret_cast<const float4*>(src + off);
    uint4 u = make_uint4(f2tf(v.x), f2tf(v.y), f2tf(v.z), f2tf(v.w));
    *reinterpret_cast<uint4*>(R + (long)which * 1048576 + off) = u;
}

// ---------------------------------------------------------------------------
// Pipelined tf32 GEMM core, ldmatrix fragments, NO CVT (inputs pre-rounded).
// NT layout (both operands K-contiguous). LDS row stride 36 floats.
// ---------------------------------------------------------------------------
template <int BM, int BN, int WM, int WN, int TPB>
DINLINE void core_ldsm(const float* __restrict__ Ab, int lda,
                       const float* __restrict__ Bb, int ldb, int K,
                       float* sA, float* sB,
                       float (&acc)[WM / 16][WN / 8][4])
{
    constexpr int LDS = 36, BK = 32, S = 3;
    constexpr int WNC = BN / WN;
    constexpr int MT = WM / 16, NT = WN / 8, NP = NT / 2;
    const int tid = threadIdx.x, lane = tid & 31, w = tid >> 5;
    const int wn = w % WNC, wm = w / WNC;
    const int mat = lane >> 3, lr = lane & 7;

    const uint32_t sAu = smem_u32(sA), sBu = smem_u32(sB);
    // A-frag tiles: mat&1 -> +8 rows, mat>>1 -> +4 k-cols
    const uint32_t aoff = (uint32_t)(((wm * WM + (mat & 1) * 8 + lr) * LDS
                                      + (mat >> 1) * 4) * 4);
    // B-frag pair tiles: mat>>1 -> +8 n-rows (next frag), mat&1 -> +4 k-cols
    const uint32_t boff = (uint32_t)(((wn * WN + (mat >> 1) * 8 + lr) * LDS
                                      + (mat & 1) * 4) * 4);

    auto load_stage = [&](int tt, int st) {
        const float* Ak = Ab + tt * BK;
        const float* Bk = Bb + tt * BK;
        float* dA = sA + st * BM * LDS;
        float* dB = sB + st * BN * LDS;
#pragma unroll
        for (int idx = tid; idx < BM * 8; idx += TPB) {
            int r = idx >> 3, c = (idx & 7) << 2;
            cpa16(dA + r * LDS + c, Ak + (long)r * lda + c);
        }
#pragma unroll
        for (int idx = tid; idx < BN * 8; idx += TPB) {
            int r = idx >> 3, c = (idx & 7) << 2;
            cpa16(dB + r * LDS + c, Bk + (long)r * ldb + c);
        }
    };

    const int T = K / BK;
#pragma unroll
    for (int tt = 0; tt < S - 1; tt++) {
        if (tt < T) load_stage(tt, tt);
        cpa_commit();
    }

    for (int tt = 0; tt < T; tt++) {
        cpa_wait<S - 2>();
        __syncthreads();
        int tn = tt + S - 1;
        if (tn < T) load_stage(tn, tn % S);
        cpa_commit();

        const uint32_t aSt = sAu + (tt % S) * BM * LDS * 4;
        const uint32_t bSt = sBu + (tt % S) * BN * LDS * 4;
#pragma unroll
        for (int ks = 0; ks < 4; ks++) {
            uint32_t af[MT][4];
#pragma unroll
            for (int mt = 0; mt < MT; mt++)
                ldsm4(af[mt], aSt + aoff + mt * (16 * LDS * 4) + ks * 32);
#pragma unroll
            for (int p = 0; p < NP; p++) {
                uint32_t bf[4];
                ldsm4(bf, bSt + boff + p * (16 * LDS * 4) + ks * 32);
#pragma unroll
                for (int mt = 0; mt < MT; mt++) {
                    mma8(acc[mt][2 * p], af[mt], bf);
                    mma8(acc[mt][2 * p + 1], af[mt], bf + 2);
                }
            }
        }
    }
}

// ---------------------------------------------------------------------------
// Projections: 4 GEMMs x 64 tiles of 128x128, 128 threads, 64x64 warp tiles.
// z=0 Q(+bias,tf32), z=1 K(tf32), z=2 V(transposed,tf32), z=3 G(sigmoid,f32)
// ---------------------------------------------------------------------------
__global__ __launch_bounds__(128, 2) void proj_k(
    const float* __restrict__ R, const float* __restrict__ bq,
    float* __restrict__ Q, float* __restrict__ Kp,
    float* __restrict__ Vt, float* __restrict__ G)
{
    extern __shared__ float sm[];
    float* sA = sm;
    float* sB = sm + 3 * 128 * 36;
    const int z = blockIdx.z;
    const long bm0 = (long)blockIdx.x * 128, bn0 = (long)blockIdx.y * 128;
    const float* A = R + ((z == 0 || z == 3) ? 0L : 1L) * 1048576 + bm0 * 1024;
    const float* B = R + (long)(z + 2) * 1048576 + bn0 * 1024;

    float acc[4][8][4];
#pragma unroll
    for (int mt = 0; mt < 4; mt++)
#pragma unroll
        for (int nt = 0; nt < 8; nt++)
#pragma unroll
            for (int e = 0; e < 4; e++) acc[mt][nt][e] = 0.f;

    core_ldsm<128, 128, 64, 64, 128>(A, 1024, B, 1024, 1024, sA, sB, acc);

    const int tid = threadIdx.x, lane = tid & 31, w = tid >> 5;
    const int g = lane >> 2, t4 = lane & 3;
    const int wn = w & 1, wm = w >> 1;
#pragma unroll
    for (int mt = 0; mt < 4; mt++)
#pragma unroll
        for (int nt = 0; nt < 8; nt++)
#pragma unroll
            for (int e = 0; e < 4; e++) {
                long m = bm0 + wm * 64 + mt * 16 + g + ((e >> 1) ? 8 : 0);
                long n = bn0 + wn * 64 + nt * 8 + 2 * t4 + (e & 1);
                float v = acc[mt][nt][e];
                if (z == 0)      Q[m * 1024 + n] = __uint_as_float(f2tf(v + bq[n]));
                else if (z == 1) Kp[m * 1024 + n] = __uint_as_float(f2tf(v));
                else if (z == 2) Vt[n * 1024 + m] = __uint_as_float(f2tf(v));
                else             G[m * 1024 + n] = 1.f / (1.f + expf(-v));
            }
}

// ---------------------------------------------------------------------------
// Final projection: out = O_gated @ Wo^T  (O, Wo pre-rounded -> ldsm core)
// ---------------------------------------------------------------------------
__global__ __launch_bounds__(256) void fgemm_k(
    const float* __restrict__ A, const float* __restrict__ B,
    float* __restrict__ C)
{
    extern __shared__ float sm[];
    float* sA = sm;
    float* sB = sm + 3 * 64 * 36;

    const long bm0 = (long)blockIdx.x * 64, bn0 = (long)blockIdx.y * 64;
    float acc[1][4][4];
#pragma unroll
    for (int nt = 0; nt < 4; nt++)
#pragma unroll
        for (int e = 0; e < 4; e++) acc[0][nt][e] = 0.f;

    core_ldsm<64, 64, 16, 32, 256>(A + bm0 * 1024, 1024, B + bn0 * 1024, 1024,
                                   1024, sA, sB, acc);

    const int tid = threadIdx.x, lane = tid & 31, w = tid >> 5;
    const int g = lane >> 2, t4 = lane & 3;
    const int wn = w & 1, wm = w >> 1;
#pragma unroll
    for (int nt = 0; nt < 4; nt++)
#pragma unroll
        for (int e = 0; e < 4; e++) {
            long m = bm0 + wm * 16 + g + ((e >> 1) ? 8 : 0);
            long n = bn0 + wn * 32 + nt * 8 + 2 * t4 + (e & 1);
            C[m * 1024 + n] = acc[0][nt][e];
        }
}

// ---------------------------------------------------------------------------
// zgemm (standalone, near LTS cap): Z[h, m] = bias[m,:] @ Wz[:,h] + mask
// ---------------------------------------------------------------------------
__global__ __launch_bounds__(256, 2) void zgemm_k(
    const float* __restrict__ bias, const float* __restrict__ Wz,
    const float* __restrict__ mask, __nv_bfloat16* __restrict__ Zout)
{
    extern __shared__ float sm[];
    const int tid = threadIdx.x, lane = tid & 31, w = tid >> 5;
    const int g = lane >> 2, t4 = lane & 3;
    const int bz = blockIdx.x;
    float* sWzT = sm;                 // [16][132] (full K=128 resident)
    float* sA = sm + 16 * 132;        // 3 stages x [128][36]
    const float* Ab = bias + (long)bz * 128 * 128;

    for (int idx = tid; idx < 2048; idx += 256) {
        int c = idx >> 4, hh = idx & 15;
        sWzT[hh * 132 + c] = Wz[idx];
    }

    auto loadA = [&](int tt, int st) {
        const float* Ak = Ab + tt * 32;
        float* dA = sA + st * 128 * 36;
#pragma unroll
        for (int idx = tid; idx < 1024; idx += 256) {
            int r = idx >> 3, c = (idx & 7) << 2;
            cpa16(dA + r * 36 + c, Ak + (long)r * 128 + c);
        }
    };

    loadA(0, 0); cpa_commit();
    loadA(1, 1); cpa_commit();

    float acc[2][4];
#pragma unroll
    for (int nt = 0; nt < 2; nt++)
#pragma unroll
        for (int e = 0; e < 4; e++) acc[nt][e] = 0.f;

    const int wm = w;
    for (int tt = 0; tt < 4; tt++) {
        cpa_wait<1>();
        __syncthreads();
        if (tt + 2 < 4) loadA(tt + 2, (tt + 2) % 3);
        cpa_commit();

        const float* cA = sA + (tt % 3) * 128 * 36;
#pragma unroll
        for (int ks = 0; ks < 4; ks++) {
            uint32_t af[4];
            af[0] = f2tf(cA[(wm * 16 + g) * 36 + ks * 8 + t4]);
            af[1] = f2tf(cA[(wm * 16 + g + 8) * 36 + ks * 8 + t4]);
            af[2] = f2tf(cA[(wm * 16 + g) * 36 + ks * 8 + t4 + 4]);
            af[3] = f2tf(cA[(wm * 16 + g + 8) * 36 + ks * 8 + t4 + 4]);
#pragma unroll
            for (int nt = 0; nt < 2; nt++) {
                uint32_t bf[2];
                bf[0] = f2tf(sWzT[(nt * 8 + g) * 132 + tt * 32 + ks * 8 + t4]);
                bf[1] = f2tf(sWzT[(nt * 8 + g) * 132 + tt * 32 + ks * 8 + t4 + 4]);
                mma8(acc[nt], af, bf);
            }
        }
    }

#pragma unroll
    for (int nt = 0; nt < 2; nt++)
#pragma unroll
        for (int e = 0; e < 4; e++) {
            long m = (long)bz * 128 + wm * 16 + g + ((e >> 1) ? 8 : 0);
            long n = nt * 8 + 2 * t4 + (e & 1);
            float v = acc[nt][e] + (1.f - mask[m & 1023]) * -1000000.f;
            Zout[n * 1048576 + m] = __float2bfloat16(v);
        }
}

// ---------------------------------------------------------------------------
// Flash attention per (i-tile 64, head). All mma operands pre-rounded tf32;
// K/V/P fragments via ldmatrix. Z bf16. Writes O pre-rounded (gated).
// ---------------------------------------------------------------------------
#define FT 4352                     // 64*68 floats
#define ZT 5632                     // 64*88 bf16
__global__ __launch_bounds__(128) void flash_k(
    const float* __restrict__ Q, const float* __restrict__ K,
    const float* __restrict__ Vt, const __nv_bfloat16* __restrict__ Z,
    const float* __restrict__ G, float* __restrict__ O)
{
    extern __shared__ float sm[];
    __nv_bfloat16* smZ = (__nv_bfloat16*)(sm + 4 * FT);
    const uint32_t smu = smem_u32(sm);
    const int h = blockIdx.y;
    const long i0 = (long)blockIdx.x * 64;
    const int tid = threadIdx.x, w = tid >> 5, lane = tid & 31;
    const int g = lane >> 2, t4 = lane & 3;
    const int r0 = w * 16 + g;
    const int mat = lane >> 3, lr = lane & 7;
    // B-frag (K, V) ldsm offset: rows +8 for next frag, cols +4 for b1
    const uint32_t bfr = (uint32_t)((((mat >> 1) * 8 + lr) * 68 + (mat & 1) * 4) * 4);
    // A-frag (P) ldsm offset: own warp's 16 rows
    const uint32_t afr = (uint32_t)(((w * 16 + (mat & 1) * 8 + lr) * 68
                                     + (mat >> 1) * 4) * 4);

    uint32_t qa[8][4];
    {
        const uint32_t* Qb = (const uint32_t*)(Q + i0 * 1024 + h * 64);
#pragma unroll
        for (int ks = 0; ks < 8; ks++) {
            qa[ks][0] = Qb[(long)r0 * 1024 + ks * 8 + t4];
            qa[ks][1] = Qb[(long)(r0 + 8) * 1024 + ks * 8 + t4];
            qa[ks][2] = Qb[(long)r0 * 1024 + ks * 8 + t4 + 4];
            qa[ks][3] = Qb[(long)(r0 + 8) * 1024 + ks * 8 + t4 + 4];
        }
    }

    float oacc[8][4];
#pragma unroll
    for (int nt = 0; nt < 8; nt++)
#pragma unroll
        for (int e = 0; e < 4; e++) oacc[nt][e] = 0.f;
    float m0 = -1e30f, m1 = -1e30f, l0 = 0.f, l1 = 0.f;

    auto stage = [&](int jt, int b) {
        const float* Ksrc = K + (long)jt * 64 * 1024 + h * 64;
        const float* Vsrc = Vt + (long)h * 65536 + jt * 64;
        const __nv_bfloat16* Zsrc = Z + (long)h * 1048576 + i0 * 1024 + jt * 64;
        float* dK = sm + b * FT;
        float* dV = sm + (2 + b) * FT;
        __nv_bfloat16* dZ = smZ + b * ZT;
#pragma unroll
        for (int idx = tid; idx < 1024; idx += 128) {
            int r = idx >> 4, c = (idx & 15) << 2;
            cpa16(dK + r * 68 + c, Ksrc + (long)r * 1024 + c);
            cpa16(dV + r * 68 + c, Vsrc + (long)r * 1024 + c);
        }
#pragma unroll
        for (int idx = tid; idx < 512; idx += 128) {
            int r = idx >> 3, c = (idx & 7) << 3;
            cpa16(dZ + r * 88 + c, Zsrc + (long)r * 1024 + c);
        }
    };

    stage(0, 0);
    cpa_commit();

    for (int jt = 0; jt < 16; jt++) {
        const int b = jt & 1;
        cpa_wait<0>();
        __syncthreads();
        if (jt < 15) { stage(jt + 1, b ^ 1); cpa_commit(); }

        const uint32_t kbu = smu + b * FT * 4;
        const uint32_t vbu = smu + (2 + b) * FT * 4;
        const __nv_bfloat16* cZ = smZ + b * ZT;

        // S = Q K^T  (ldmatrix x4 = two b-frags per issue)
        float sacc[8][4];
#pragma unroll
        for (int nt = 0; nt < 8; nt++)
#pragma unroll
            for (int e = 0; e < 4; e++) sacc[nt][e] = 0.f;
#pragma unroll
        for (int ks = 0; ks < 8; ks++) {
#pragma unroll
            for (int p = 0; p < 4; p++) {
                uint32_t bk[4];
                ldsm4(bk, kbu + bfr + p * (16 * 68 * 4) + ks * 32);
                mma8(sacc[2 * p], qa[ks], bk);
                mma8(sacc[2 * p + 1], qa[ks], bk + 2);
            }
        }

        // scale + Z (bf16 -> f32)
#pragma unroll
        for (int nt = 0; nt < 8; nt++) {
            const float2 z0 = __bfloat1622float2(
                *reinterpret_cast<const __nv_bfloat162*>(&cZ[r0 * 88 + nt * 8 + 2 * t4]));
            const float2 z1 = __bfloat1622float2(
                *reinterpret_cast<const __nv_bfloat162*>(&cZ[(r0 + 8) * 88 + nt * 8 + 2 * t4]));
            sacc[nt][0] = fmaf(sacc[nt][0], 0.125f, z0.x);
            sacc[nt][1] = fmaf(sacc[nt][1], 0.125f, z0.y);
            sacc[nt][2] = fmaf(sacc[nt][2], 0.125f, z1.x);
            sacc[nt][3] = fmaf(sacc[nt][3], 0.125f, z1.y);
        }

        // online softmax
        float mx0 = -1e30f, mx1 = -1e30f;
#pragma unroll
        for (int nt = 0; nt < 8; nt++) {
            mx0 = fmaxf(mx0, fmaxf(sacc[nt][0], sacc[nt][1]));
            mx1 = fmaxf(mx1, fmaxf(sacc[nt][2], sacc[nt][3]));
        }
        mx0 = fmaxf(mx0, __shfl_xor_sync(0xFFFFFFFFu, mx0, 1));
        mx0 = fmaxf(mx0, __shfl_xor_sync(0xFFFFFFFFu, mx0, 2));
        mx1 = fmaxf(mx1, __shfl_xor_sync(0xFFFFFFFFu, mx1, 1));
        mx1 = fmaxf(mx1, __shfl_xor_sync(0xFFFFFFFFu, mx1, 2));

        const float mn0 = fmaxf(m0, mx0), mn1 = fmaxf(m1, mx1);
        const float a0 = __expf(m0 - mn0), a1 = __expf(m1 - mn1);
        m0 = mn0; m1 = mn1;

        float rs0 = 0.f, rs1 = 0.f;
#pragma unroll
        for (int nt = 0; nt < 8; nt++) {
            sacc[nt][0] = __expf(sacc[nt][0] - mn0);
            sacc[nt][1] = __expf(sacc[nt][1] - mn0);
            sacc[nt][2] = __expf(sacc[nt][2] - mn1);
            sacc[nt][3] = __expf(sacc[nt][3] - mn1);
            rs0 += sacc[nt][0] + sacc[nt][1];
            rs1 += sacc[nt][2] + sacc[nt][3];
        }
        rs0 += __shfl_xor_sync(0xFFFFFFFFu, rs0, 1);
        rs0 += __shfl_xor_sync(0xFFFFFFFFu, rs0, 2);
        rs1 += __shfl_xor_sync(0xFFFFFFFFu, rs1, 1);
        rs1 += __shfl_xor_sync(0xFFFFFFFFu, rs1, 2);
        l0 = l0 * a0 + rs0;
        l1 = l1 * a1 + rs1;
#pragma unroll
        for (int nt = 0; nt < 8; nt++) {
            oacc[nt][0] *= a0; oacc[nt][1] *= a0;
            oacc[nt][2] *= a1; oacc[nt][3] *= a1;
        }

        // P (tf32-rounded) overlays current K buffer
        __syncthreads();
        uint32_t* pP = (uint32_t*)(sm + b * FT);
#pragma unroll
        for (int nt = 0; nt < 8; nt++) {
            uint2 p0 = make_uint2(f2tf(sacc[nt][0]), f2tf(sacc[nt][1]));
            uint2 p1 = make_uint2(f2tf(sacc[nt][2]), f2tf(sacc[nt][3]));
            *reinterpret_cast<uint2*>(&pP[r0 * 68 + nt * 8 + 2 * t4]) = p0;
            *reinterpret_cast<uint2*>(&pP[(r0 + 8) * 68 + nt * 8 + 2 * t4]) = p1;
        }
        __syncwarp();

        // O += P @ V  (ldmatrix for both operands)
#pragma unroll
        for (int ks = 0; ks < 8; ks++) {
            uint32_t pa[4];
            ldsm4(pa, kbu + afr + ks * 32);
#pragma unroll
            for (int p = 0; p < 4; p++) {
                uint32_t bv[4];
                ldsm4(bv, vbu + bfr + p * (16 * 68 * 4) + ks * 32);
                mma8(oacc[2 * p], pa, bv);
                mma8(oacc[2 * p + 1], pa, bv + 2);
            }
        }
    }

    // epilogue: o/l * G, pre-rounded to tf32 for the final ldsm GEMM
    const float iv0 = 1.f / l0, iv1 = 1.f / l1;
#pragma unroll
    for (int nt = 0; nt < 8; nt++) {
        const int c = h * 64 + nt * 8 + 2 * t4;
        const long ro0 = (i0 + r0) * 1024 + c;
        const long ro1 = (i0 + r0 + 8) * 1024 + c;
        const float2 g0 = *reinterpret_cast<const float2*>(&G[ro0]);
        const float2 g1 = *reinterpret_cast<const float2*>(&G[ro1]);
        *reinterpret_cast<uint2*>(&O[ro0]) =
            make_uint2(f2tf(oacc[nt][0] * iv0 * g0.x), f2tf(oacc[nt][1] * iv0 * g0.y));
        *reinterpret_cast<uint2*>(&O[ro1]) =
            make_uint2(f2tf(oacc[nt][2] * iv1 * g1.x), f2tf(oacc[nt][3] * iv1 * g1.y));
    }
}

// ---------------------------------------------------------------------------
// Launch
// ---------------------------------------------------------------------------
extern "C" void kernel_launch(void* const* d_in, const int* in_sizes, int n_in,
                              void* d_out, int out_size)
{
    const float* s    = (const float*)d_in[0];
    const float* k_in = (const float*)d_in[1];
    const float* mask = (const float*)d_in[2];
    const float* bias = (const float*)d_in[3];
    const float* Wq   = (const float*)d_in[4];
    const float* bq   = (const float*)d_in[5];
    const float* Wk   = (const float*)d_in[6];
    const float* Wv   = (const float*)d_in[7];
    const float* Wg   = (const float*)d_in[8];
    const float* Wo   = (const float*)d_in[9];
    const float* Wz   = (const float*)d_in[10];
    float* out = (float*)d_out;

    float *Q, *Kp, *Vt, *G, *O, *R;
    __nv_bfloat16* Z;
    cudaGetSymbolAddress((void**)&Q,  g_Q);
    cudaGetSymbolAddress((void**)&Kp, g_K);
    cudaGetSymbolAddress((void**)&Vt, g_Vt);
    cudaGetSymbolAddress((void**)&G,  g_G);
    cudaGetSymbolAddress((void**)&O,  g_O);
    cudaGetSymbolAddress((void**)&Z,  g_Z);
    cudaGetSymbolAddress((void**)&R,  g_R);

    const int SM_PROJ  = 3 * (128 + 128) * 36 * 4;       // 110592
    const int SM_ZG    = (16 * 132 + 3 * 128 * 36) * 4;  //  63744
    const int SM_6464  = 3 * (64 + 64) * 36 * 4;         //  55296
    const int SM_FLASH = 4 * FT * 4 + 2 * ZT * 2;        //  92160

    cudaFuncSetAttribute((const void*)proj_k,
                         cudaFuncAttributeMaxDynamicSharedMemorySize, SM_PROJ);
    cudaFuncSetAttribute((const void*)zgemm_k,
                         cudaFuncAttributeMaxDynamicSharedMemorySize, SM_ZG);
    cudaFuncSetAttribute((const void*)fgemm_k,
                         cudaFuncAttributeMaxDynamicSharedMemorySize, SM_6464);
    cudaFuncSetAttribute((const void*)flash_k,
                         cudaFuncAttributeMaxDynamicSharedMemorySize, SM_FLASH);

    // pre-round s, kin, Wq, Wk, Wv, Wg, Wo to tf32 (rna)
    round7_k<<<7168, 256>>>(s, k_in, Wq, Wk, Wv, Wg, Wo, R);

    // projections: Q(+bias), K, V(transposed), G(sigmoid) — ldsm core
    proj_k<<<dim3(8, 8, 4), 128, SM_PROJ>>>(R, bq, Q, Kp, Vt, G);

    // Z[h,i,j] = bias[i,j,:] @ Wz[:,h] + mask  (bf16 out, DRAM-bound)
    zgemm_k<<<8192, 256, SM_ZG>>>(bias, Wz, mask, Z);

    // fused attention + gating (writes O tf32-rounded)
    flash_k<<<dim3(16, 16), 128, SM_FLASH>>>(Q, Kp, Vt, Z, G, O);

    // out = O_gated @ Wo^T — ldsm core, no CVT
    fgemm_k<<<dim3(16, 16), 256, SM_6464>>>(O, R + 6 * 1048576, out);
}

// round 12
// speedup vs baseline: 1.0485x; 1.0485x over previous
#include <cuda_runtime.h>
#include <cuda_bf16.h>
#include <cstdint>

#define DINLINE __device__ __forceinline__

// ---------------------------------------------------------------------------
// helpers
// ---------------------------------------------------------------------------
DINLINE uint32_t f2tf(float x) {
    uint32_t r;
    asm("cvt.rna.tf32.f32 %0, %1;" : "=r"(r) : "f"(x));
    return r;
}

DINLINE void mma8(float c[4], const uint32_t a[4], const uint32_t b[2]) {
    asm volatile(
        "mma.sync.aligned.m16n8k8.row.col.f32.tf32.tf32.f32 "
        "{%0,%1,%2,%3}, {%4,%5,%6,%7}, {%8,%9}, {%0,%1,%2,%3};"
        : "+f"(c[0]), "+f"(c[1]), "+f"(c[2]), "+f"(c[3])
        : "r"(a[0]), "r"(a[1]), "r"(a[2]), "r"(a[3]), "r"(b[0]), "r"(b[1]));
}

DINLINE void ldsm4(uint32_t r[4], uint32_t addr) {
    asm volatile("ldmatrix.sync.aligned.m8n8.x4.shared.b16 {%0,%1,%2,%3}, [%4];"
                 : "=r"(r[0]), "=r"(r[1]), "=r"(r[2]), "=r"(r[3]) : "r"(addr));
}

DINLINE void cpa16(void* sm, const void* g) {
    uint32_t a = (uint32_t)__cvta_generic_to_shared(sm);
    asm volatile("cp.async.cg.shared.global [%0], [%1], 16;\n" :: "r"(a), "l"(g));
}
DINLINE void cpa_commit() { asm volatile("cp.async.commit_group;\n"); }
template <int N> DINLINE void cpa_wait() { asm volatile("cp.async.wait_group %0;\n" :: "n"(N)); }

DINLINE uint32_t smem_u32(const void* p) {
    uint32_t a;
    asm("{ .reg .u64 t; cvta.to.shared.u64 t, %1; cvt.u32.u64 %0, t; }"
        : "=r"(a) : "l"(p));
    return a;
}

// ---------------------------------------------------------------------------
// Scratch
// ---------------------------------------------------------------------------
__device__ float g_Q[1048576];     // tf32-rounded bits
__device__ float g_K[1048576];     // tf32-rounded bits
__device__ float g_Vt[1048576];    // [h][d][j], tf32-rounded bits
__device__ float g_G[1048576];
__device__ float g_O[1048576];     // tf32-rounded bits (gated)
__device__ __nv_bfloat16 g_Z[16777216];  // [h][i][j] bf16
__device__ float g_R[7340032];     // tf32-rounded: s, kin, Wq, Wk, Wv, Wg, Wo

// ---------------------------------------------------------------------------
// Pre-round 7 x 1M-float buffers to tf32 (rna)
// ---------------------------------------------------------------------------
__global__ void round7_k(const float* __restrict__ s, const float* __restrict__ kin,
                         const float* __restrict__ Wq, const float* __restrict__ Wk,
                         const float* __restrict__ Wv, const float* __restrict__ Wg,
                         const float* __restrict__ Wo, float* __restrict__ R)
{
    long i = (long)blockIdx.x * 256 + threadIdx.x;   // float4 index
    int which = (int)(i >> 18);
    long off = (i & 262143) << 2;
    const float* src = which == 0 ? s : which == 1 ? kin : which == 2 ? Wq
                     : which == 3 ? Wk : which == 4 ? Wv : which == 5 ? Wg : Wo;
    float4 v = *reinterpret_cast<const float4*>(src + off);
    uint4 u = make_uint4(f2tf(v.x), f2tf(v.y), f2tf(v.z), f2tf(v.w));
    *reinterpret_cast<uint4*>(R + (long)which * 1048576 + off) = u;
}

// ---------------------------------------------------------------------------
// Pipelined tf32 GEMM core, ldmatrix fragments, NO CVT (inputs pre-rounded).
// ---------------------------------------------------------------------------
template <int BM, int BN, int WM, int WN, int TPB>
DINLINE void core_ldsm(const float* __restrict__ Ab, int lda,
                       const float* __restrict__ Bb, int ldb, int K,
                       float* sA, float* sB,
                       float (&acc)[WM / 16][WN / 8][4])
{
    constexpr int LDS = 36, BK = 32, S = 3;
    constexpr int WNC = BN / WN;
    constexpr int MT = WM / 16, NT = WN / 8, NP = NT / 2;
    const int tid = threadIdx.x, lane = tid & 31, w = tid >> 5;
    const int wn = w % WNC, wm = w / WNC;
    const int mat = lane >> 3, lr = lane & 7;

    const uint32_t sAu = smem_u32(sA), sBu = smem_u32(sB);
    const uint32_t aoff = (uint32_t)(((wm * WM + (mat & 1) * 8 + lr) * LDS
                                      + (mat >> 1) * 4) * 4);
    const uint32_t boff = (uint32_t)(((wn * WN + (mat >> 1) * 8 + lr) * LDS
                                      + (mat & 1) * 4) * 4);

    auto load_stage = [&](int tt, int st) {
        const float* Ak = Ab + tt * BK;
        const float* Bk = Bb + tt * BK;
        float* dA = sA + st * BM * LDS;
        float* dB = sB + st * BN * LDS;
#pragma unroll
        for (int idx = tid; idx < BM * 8; idx += TPB) {
            int r = idx >> 3, c = (idx & 7) << 2;
            cpa16(dA + r * LDS + c, Ak + (long)r * lda + c);
        }
#pragma unroll
        for (int idx = tid; idx < BN * 8; idx += TPB) {
            int r = idx >> 3, c = (idx & 7) << 2;
            cpa16(dB + r * LDS + c, Bk + (long)r * ldb + c);
        }
    };

    const int T = K / BK;
#pragma unroll
    for (int tt = 0; tt < S - 1; tt++) {
        if (tt < T) load_stage(tt, tt);
        cpa_commit();
    }

    for (int tt = 0; tt < T; tt++) {
        cpa_wait<S - 2>();
        __syncthreads();
        int tn = tt + S - 1;
        if (tn < T) load_stage(tn, tn % S);
        cpa_commit();

        const uint32_t aSt = sAu + (tt % S) * BM * LDS * 4;
        const uint32_t bSt = sBu + (tt % S) * BN * LDS * 4;
#pragma unroll
        for (int ks = 0; ks < 4; ks++) {
            uint32_t af[MT][4];
#pragma unroll
            for (int mt = 0; mt < MT; mt++)
                ldsm4(af[mt], aSt + aoff + mt * (16 * LDS * 4) + ks * 32);
#pragma unroll
            for (int p = 0; p < NP; p++) {
                uint32_t bf[4];
                ldsm4(bf, bSt + boff + p * (16 * LDS * 4) + ks * 32);
#pragma unroll
                for (int mt = 0; mt < MT; mt++) {
                    mma8(acc[mt][2 * p], af[mt], bf);
                    mma8(acc[mt][2 * p + 1], af[mt], bf + 2);
                }
            }
        }
    }
}

// ---------------------------------------------------------------------------
// FAT KERNEL: proj (bids 0..255) + zgemm (bids 256..8447).
// proj: 128x128 tiles, ldsm core, pre-rounded R (no CVT).
// zgemm: all 4 K-stages prefetched up-front -> 64KB in flight per CTA so the
// ~40 co-resident zgemm slots can stream bias at DRAM cap UNDER the proj phase.
// ---------------------------------------------------------------------------
__global__ __launch_bounds__(256, 2) void fused_pz_k(
    const float* __restrict__ R, const float* __restrict__ bq,
    const float* __restrict__ bias, const float* __restrict__ Wz,
    const float* __restrict__ mask,
    float* __restrict__ Q, float* __restrict__ Kp,
    float* __restrict__ Vt, float* __restrict__ G,
    __nv_bfloat16* __restrict__ Zout)
{
    extern __shared__ float sm[];
    const int bx = blockIdx.x;
    const int tid = threadIdx.x, lane = tid & 31, w = tid >> 5;
    const int g = lane >> 2, t4 = lane & 3;

    if (bx < 256) {
        // ---------------- proj path -------------------------------------
        float* sA = sm;
        float* sB = sm + 3 * 128 * 36;
        const int z = bx >> 6, rem = bx & 63;
        const long bm0 = (long)(rem & 7) * 128, bn0 = (long)(rem >> 3) * 128;
        const float* A = R + ((z == 0 || z == 3) ? 0L : 1L) * 1048576 + bm0 * 1024;
        const float* B = R + (long)(z + 2) * 1048576 + bn0 * 1024;

        float acc[2][8][4];
#pragma unroll
        for (int mt = 0; mt < 2; mt++)
#pragma unroll
            for (int nt = 0; nt < 8; nt++)
#pragma unroll
                for (int e = 0; e < 4; e++) acc[mt][nt][e] = 0.f;

        core_ldsm<128, 128, 32, 64, 256>(A, 1024, B, 1024, 1024, sA, sB, acc);

        const int wn = w & 1, wm = w >> 1;
#pragma unroll
        for (int mt = 0; mt < 2; mt++)
#pragma unroll
            for (int nt = 0; nt < 8; nt++)
#pragma unroll
                for (int e = 0; e < 4; e++) {
                    long m = bm0 + wm * 32 + mt * 16 + g + ((e >> 1) ? 8 : 0);
                    long n = bn0 + wn * 64 + nt * 8 + 2 * t4 + (e & 1);
                    float v = acc[mt][nt][e];
                    if (z == 0)      Q[m * 1024 + n] = __uint_as_float(f2tf(v + bq[n]));
                    else if (z == 1) Kp[m * 1024 + n] = __uint_as_float(f2tf(v));
                    else if (z == 2) Vt[n * 1024 + m] = __uint_as_float(f2tf(v));
                    else             G[m * 1024 + n] = 1.f / (1.f + expf(-v));
                }
    } else {
        // ---------------- zgemm path: Z[h, m] = bias[m,:] @ Wz[:,h] -----
        const int bz = bx - 256;
        float* sWzT = sm;                 // [16][132] (K=128 resident)
        float* sA = sm + 16 * 132;        // 4 stages x [128][36]
        const float* Ab = bias + (long)bz * 128 * 128;

        // issue ALL 4 K-stages immediately: 64KB in flight per CTA
#pragma unroll
        for (int st = 0; st < 4; st++) {
            const float* Ak = Ab + st * 32;
            float* dA = sA + st * 128 * 36;
#pragma unroll
            for (int idx = tid; idx < 1024; idx += 256) {
                int r = idx >> 3, c = (idx & 7) << 2;
                cpa16(dA + r * 36 + c, Ak + (long)r * 128 + c);
            }
            cpa_commit();
        }

        // WzT while loads fly (L2-hot after first CTAs)
        for (int idx = tid; idx < 2048; idx += 256) {
            int c = idx >> 4, hh = idx & 15;
            sWzT[hh * 132 + c] = Wz[idx];
        }

        float acc[2][4];
#pragma unroll
        for (int nt = 0; nt < 2; nt++)
#pragma unroll
            for (int e = 0; e < 4; e++) acc[nt][e] = 0.f;

        const int wm = w;
#pragma unroll
        for (int tt = 0; tt < 4; tt++) {
            if (tt == 0) cpa_wait<3>();
            else if (tt == 1) cpa_wait<2>();
            else if (tt == 2) cpa_wait<1>();
            else cpa_wait<0>();
            __syncthreads();

            const float* cA = sA + tt * 128 * 36;
#pragma unroll
            for (int ks = 0; ks < 4; ks++) {
                uint32_t af[4];
                af[0] = f2tf(cA[(wm * 16 + g) * 36 + ks * 8 + t4]);
                af[1] = f2tf(cA[(wm * 16 + g + 8) * 36 + ks * 8 + t4]);
                af[2] = f2tf(cA[(wm * 16 + g) * 36 + ks * 8 + t4 + 4]);
                af[3] = f2tf(cA[(wm * 16 + g + 8) * 36 + ks * 8 + t4 + 4]);
#pragma unroll
                for (int nt = 0; nt < 2; nt++) {
                    uint32_t bf[2];
                    bf[0] = f2tf(sWzT[(nt * 8 + g) * 132 + tt * 32 + ks * 8 + t4]);
                    bf[1] = f2tf(sWzT[(nt * 8 + g) * 132 + tt * 32 + ks * 8 + t4 + 4]);
                    mma8(acc[nt], af, bf);
                }
            }
        }

#pragma unroll
        for (int nt = 0; nt < 2; nt++)
#pragma unroll
            for (int e = 0; e < 4; e++) {
                long m = (long)bz * 128 + wm * 16 + g + ((e >> 1) ? 8 : 0);
                long n = nt * 8 + 2 * t4 + (e & 1);
                float v = acc[nt][e] + (1.f - mask[m & 1023]) * -1000000.f;
                Zout[n * 1048576 + m] = __float2bfloat16(v);
            }
    }
}

// ---------------------------------------------------------------------------
// Final projection: out = O_gated @ Wo^T  (both pre-rounded -> ldsm core)
// ---------------------------------------------------------------------------
__global__ __launch_bounds__(256) void fgemm_k(
    const float* __restrict__ A, const float* __restrict__ B,
    float* __restrict__ C)
{
    extern __shared__ float sm[];
    float* sA = sm;
    float* sB = sm + 3 * 64 * 36;

    const long bm0 = (long)blockIdx.x * 64, bn0 = (long)blockIdx.y * 64;
    float acc[1][4][4];
#pragma unroll
    for (int nt = 0; nt < 4; nt++)
#pragma unroll
        for (int e = 0; e < 4; e++) acc[0][nt][e] = 0.f;

    core_ldsm<64, 64, 16, 32, 256>(A + bm0 * 1024, 1024, B + bn0 * 1024, 1024,
                                   1024, sA, sB, acc);

    const int tid = threadIdx.x, lane = tid & 31, w = tid >> 5;
    const int g = lane >> 2, t4 = lane & 3;
    const int wn = w & 1, wm = w >> 1;
#pragma unroll
    for (int nt = 0; nt < 4; nt++)
#pragma unroll
        for (int e = 0; e < 4; e++) {
            long m = bm0 + wm * 16 + g + ((e >> 1) ? 8 : 0);
            long n = bn0 + wn * 32 + nt * 8 + 2 * t4 + (e & 1);
            C[m * 1024 + n] = acc[0][nt][e];
        }
}

// ---------------------------------------------------------------------------
// Flash attention per (i-tile 64, head). Pre-rounded tf32 operands,
// ldmatrix fragments, Z bf16, gated epilogue writes O pre-rounded.
// ---------------------------------------------------------------------------
#define FT 4352                     // 64*68 floats
#define ZT 5632                     // 64*88 bf16
__global__ __launch_bounds__(128) void flash_k(
    const float* __restrict__ Q, const float* __restrict__ K,
    const float* __restrict__ Vt, const __nv_bfloat16* __restrict__ Z,
    const float* __restrict__ G, float* __restrict__ O)
{
    extern __shared__ float sm[];
    __nv_bfloat16* smZ = (__nv_bfloat16*)(sm + 4 * FT);
    const uint32_t smu = smem_u32(sm);
    const int h = blockIdx.y;
    const long i0 = (long)blockIdx.x * 64;
    const int tid = threadIdx.x, w = tid >> 5, lane = tid & 31;
    const int g = lane >> 2, t4 = lane & 3;
    const int r0 = w * 16 + g;
    const int mat = lane >> 3, lr = lane & 7;
    const uint32_t bfr = (uint32_t)((((mat >> 1) * 8 + lr) * 68 + (mat & 1) * 4) * 4);
    const uint32_t afr = (uint32_t)(((w * 16 + (mat & 1) * 8 + lr) * 68
                                     + (mat >> 1) * 4) * 4);

    uint32_t qa[8][4];
    {
        const uint32_t* Qb = (const uint32_t*)(Q + i0 * 1024 + h * 64);
#pragma unroll
        for (int ks = 0; ks < 8; ks++) {
            qa[ks][0] = Qb[(long)r0 * 1024 + ks * 8 + t4];
            qa[ks][1] = Qb[(long)(r0 + 8) * 1024 + ks * 8 + t4];
            qa[ks][2] = Qb[(long)r0 * 1024 + ks * 8 + t4 + 4];
            qa[ks][3] = Qb[(long)(r0 + 8) * 1024 + ks * 8 + t4 + 4];
        }
    }

    float oacc[8][4];
#pragma unroll
    for (int nt = 0; nt < 8; nt++)
#pragma unroll
        for (int e = 0; e < 4; e++) oacc[nt][e] = 0.f;
    float m0 = -1e30f, m1 = -1e30f, l0 = 0.f, l1 = 0.f;

    auto stage = [&](int jt, int b) {
        const float* Ksrc = K + (long)jt * 64 * 1024 + h * 64;
        const float* Vsrc = Vt + (long)h * 65536 + jt * 64;
        const __nv_bfloat16* Zsrc = Z + (long)h * 1048576 + i0 * 1024 + jt * 64;
        float* dK = sm + b * FT;
        float* dV = sm + (2 + b) * FT;
        __nv_bfloat16* dZ = smZ + b * ZT;
#pragma unroll
        for (int idx = tid; idx < 1024; idx += 128) {
            int r = idx >> 4, c = (idx & 15) << 2;
            cpa16(dK + r * 68 + c, Ksrc + (long)r * 1024 + c);
            cpa16(dV + r * 68 + c, Vsrc + (long)r * 1024 + c);
        }
#pragma unroll
        for (int idx = tid; idx < 512; idx += 128) {
            int r = idx >> 3, c = (idx & 7) << 3;
            cpa16(dZ + r * 88 + c, Zsrc + (long)r * 1024 + c);
        }
    };

    stage(0, 0);
    cpa_commit();

    for (int jt = 0; jt < 16; jt++) {
        const int b = jt & 1;
        cpa_wait<0>();
        __syncthreads();
        if (jt < 15) { stage(jt + 1, b ^ 1); cpa_commit(); }

        const uint32_t kbu = smu + b * FT * 4;
        const uint32_t vbu = smu + (2 + b) * FT * 4;
        const __nv_bfloat16* cZ = smZ + b * ZT;

        float sacc[8][4];
#pragma unroll
        for (int nt = 0; nt < 8; nt++)
#pragma unroll
            for (int e = 0; e < 4; e++) sacc[nt][e] = 0.f;
#pragma unroll
        for (int ks = 0; ks < 8; ks++) {
#pragma unroll
            for (int p = 0; p < 4; p++) {
                uint32_t bk[4];
                ldsm4(bk, kbu + bfr + p * (16 * 68 * 4) + ks * 32);
                mma8(sacc[2 * p], qa[ks], bk);
                mma8(sacc[2 * p + 1], qa[ks], bk + 2);
            }
        }

#pragma unroll
        for (int nt = 0; nt < 8; nt++) {
            const float2 z0 = __bfloat1622float2(
                *reinterpret_cast<const __nv_bfloat162*>(&cZ[r0 * 88 + nt * 8 + 2 * t4]));
            const float2 z1 = __bfloat1622float2(
                *reinterpret_cast<const __nv_bfloat162*>(&cZ[(r0 + 8) * 88 + nt * 8 + 2 * t4]));
            sacc[nt][0] = fmaf(sacc[nt][0], 0.125f, z0.x);
            sacc[nt][1] = fmaf(sacc[nt][1], 0.125f, z0.y);
            sacc[nt][2] = fmaf(sacc[nt][2], 0.125f, z1.x);
            sacc[nt][3] = fmaf(sacc[nt][3], 0.125f, z1.y);
        }

        float mx0 = -1e30f, mx1 = -1e30f;
#pragma unroll
        for (int nt = 0; nt < 8; nt++) {
            mx0 = fmaxf(mx0, fmaxf(sacc[nt][0], sacc[nt][1]));
            mx1 = fmaxf(mx1, fmaxf(sacc[nt][2], sacc[nt][3]));
        }
        mx0 = fmaxf(mx0, __shfl_xor_sync(0xFFFFFFFFu, mx0, 1));
        mx0 = fmaxf(mx0, __shfl_xor_sync(0xFFFFFFFFu, mx0, 2));
        mx1 = fmaxf(mx1, __shfl_xor_sync(0xFFFFFFFFu, mx1, 1));
        mx1 = fmaxf(mx1, __shfl_xor_sync(0xFFFFFFFFu, mx1, 2));

        const float mn0 = fmaxf(m0, mx0), mn1 = fmaxf(m1, mx1);
        const float a0 = __expf(m0 - mn0), a1 = __expf(m1 - mn1);
        m0 = mn0; m1 = mn1;

        float rs0 = 0.f, rs1 = 0.f;
#pragma unroll
        for (int nt = 0; nt < 8; nt++) {
            sacc[nt][0] = __expf(sacc[nt][0] - mn0);
            sacc[nt][1] = __expf(sacc[nt][1] - mn0);
            sacc[nt][2] = __expf(sacc[nt][2] - mn1);
            sacc[nt][3] = __expf(sacc[nt][3] - mn1);
            rs0 += sacc[nt][0] + sacc[nt][1];
            rs1 += sacc[nt][2] + sacc[nt][3];
        }
        rs0 += __shfl_xor_sync(0xFFFFFFFFu, rs0, 1);
        rs0 += __shfl_xor_sync(0xFFFFFFFFu, rs0, 2);
        rs1 += __shfl_xor_sync(0xFFFFFFFFu, rs1, 1);
        rs1 += __shfl_xor_sync(0xFFFFFFFFu, rs1, 2);
        l0 = l0 * a0 + rs0;
        l1 = l1 * a1 + rs1;
#pragma unroll
        for (int nt = 0; nt < 8; nt++) {
            oacc[nt][0] *= a0; oacc[nt][1] *= a0;
            oacc[nt][2] *= a1; oacc[nt][3] *= a1;
        }

        __syncthreads();
        uint32_t* pP = (uint32_t*)(sm + b * FT);
#pragma unroll
        for (int nt = 0; nt < 8; nt++) {
            uint2 p0 = make_uint2(f2tf(sacc[nt][0]), f2tf(sacc[nt][1]));
            uint2 p1 = make_uint2(f2tf(sacc[nt][2]), f2tf(sacc[nt][3]));
            *reinterpret_cast<uint2*>(&pP[r0 * 68 + nt * 8 + 2 * t4]) = p0;
            *reinterpret_cast<uint2*>(&pP[(r0 + 8) * 68 + nt * 8 + 2 * t4]) = p1;
        }
        __syncwarp();

#pragma unroll
        for (int ks = 0; ks < 8; ks++) {
            uint32_t pa[4];
            ldsm4(pa, kbu + afr + ks * 32);
#pragma unroll
            for (int p = 0; p < 4; p++) {
                uint32_t bv[4];
                ldsm4(bv, vbu + bfr + p * (16 * 68 * 4) + ks * 32);
                mma8(oacc[2 * p], pa, bv);
                mma8(oacc[2 * p + 1], pa, bv + 2);
            }
        }
    }

    const float iv0 = 1.f / l0, iv1 = 1.f / l1;
#pragma unroll
    for (int nt = 0; nt < 8; nt++) {
        const int c = h * 64 + nt * 8 + 2 * t4;
        const long ro0 = (i0 + r0) * 1024 + c;
        const long ro1 = (i0 + r0 + 8) * 1024 + c;
        const float2 g0 = *reinterpret_cast<const float2*>(&G[ro0]);
        const float2 g1 = *reinterpret_cast<const float2*>(&G[ro1]);
        *reinterpret_cast<uint2*>(&O[ro0]) =
            make_uint2(f2tf(oacc[nt][0] * iv0 * g0.x), f2tf(oacc[nt][1] * iv0 * g0.y));
        *reinterpret_cast<uint2*>(&O[ro1]) =
            make_uint2(f2tf(oacc[nt][2] * iv1 * g1.x), f2tf(oacc[nt][3] * iv1 * g1.y));
    }
}

// ---------------------------------------------------------------------------
// Launch
// ---------------------------------------------------------------------------
extern "C" void kernel_launch(void* const* d_in, const int* in_sizes, int n_in,
                              void* d_out, int out_size)
{
    const float* s    = (const float*)d_in[0];
    const float* k_in = (const float*)d_in[1];
    const float* mask = (const float*)d_in[2];
    const float* bias = (const float*)d_in[3];
    const float* Wq   = (const float*)d_in[4];
    const float* bq   = (const float*)d_in[5];
    const float* Wk   = (const float*)d_in[6];
    const float* Wv   = (const float*)d_in[7];
    const float* Wg   = (const float*)d_in[8];
    const float* Wo   = (const float*)d_in[9];
    const float* Wz   = (const float*)d_in[10];
    float* out = (float*)d_out;

    float *Q, *Kp, *Vt, *G, *O, *R;
    __nv_bfloat16* Z;
    cudaGetSymbolAddress((void**)&Q,  g_Q);
    cudaGetSymbolAddress((void**)&Kp, g_K);
    cudaGetSymbolAddress((void**)&Vt, g_Vt);
    cudaGetSymbolAddress((void**)&G,  g_G);
    cudaGetSymbolAddress((void**)&O,  g_O);
    cudaGetSymbolAddress((void**)&Z,  g_Z);
    cudaGetSymbolAddress((void**)&R,  g_R);

    const int SM_FAT   = 3 * (128 + 128) * 36 * 4;       // 110592
    const int SM_6464  = 3 * (64 + 64) * 36 * 4;         //  55296
    const int SM_FLASH = 4 * FT * 4 + 2 * ZT * 2;        //  92160

    cudaFuncSetAttribute((const void*)fused_pz_k,
                         cudaFuncAttributeMaxDynamicSharedMemorySize, SM_FAT);
    cudaFuncSetAttribute((const void*)fgemm_k,
                         cudaFuncAttributeMaxDynamicSharedMemorySize, SM_6464);
    cudaFuncSetAttribute((const void*)flash_k,
                         cudaFuncAttributeMaxDynamicSharedMemorySize, SM_FLASH);

    // pre-round s, kin, Wq, Wk, Wv, Wg, Wo to tf32 (rna)
    round7_k<<<7168, 256>>>(s, k_in, Wq, Wk, Wv, Wg, Wo, R);

    // proj (256 CTAs, ldsm core) + zgemm (8192 CTAs, deep prefetch) overlapped
    fused_pz_k<<<8448, 256, SM_FAT>>>(R, bq, bias, Wz, mask, Q, Kp, Vt, G, Z);

    // fused attention + gating (writes O tf32-rounded)
    flash_k<<<dim3(16, 16), 128, SM_FLASH>>>(Q, Kp, Vt, Z, G, O);

    // out = O_gated @ Wo^T — ldsm core, no CVT
    fgemm_k<<<dim3(16, 16), 256, SM_6464>>>(O, R + 6 * 1048576, out);
}

// round 15
// speedup vs baseline: 1.0593x; 1.0104x over previous
#include <cuda_runtime.h>
#include <cuda_bf16.h>
#include <cstdint>

#define DINLINE __device__ __forceinline__

// ---------------------------------------------------------------------------
// helpers
// ---------------------------------------------------------------------------
DINLINE uint32_t f2tf(float x) {
    uint32_t r;
    asm("cvt.rna.tf32.f32 %0, %1;" : "=r"(r) : "f"(x));
    return r;
}

DINLINE void mma8(float c[4], const uint32_t a[4], const uint32_t b[2]) {
    asm volatile(
        "mma.sync.aligned.m16n8k8.row.col.f32.tf32.tf32.f32 "
        "{%0,%1,%2,%3}, {%4,%5,%6,%7}, {%8,%9}, {%0,%1,%2,%3};"
        : "+f"(c[0]), "+f"(c[1]), "+f"(c[2]), "+f"(c[3])
        : "r"(a[0]), "r"(a[1]), "r"(a[2]), "r"(a[3]), "r"(b[0]), "r"(b[1]));
}

DINLINE void ldsm4(uint32_t r[4], uint32_t addr) {
    asm volatile("ldmatrix.sync.aligned.m8n8.x4.shared.b16 {%0,%1,%2,%3}, [%4];"
                 : "=r"(r[0]), "=r"(r[1]), "=r"(r[2]), "=r"(r[3]) : "r"(addr));
}

DINLINE void cpa16(void* sm, const void* g) {
    uint32_t a = (uint32_t)__cvta_generic_to_shared(sm);
    asm volatile("cp.async.cg.shared.global [%0], [%1], 16;\n" :: "r"(a), "l"(g));
}
DINLINE void cpa_commit() { asm volatile("cp.async.commit_group;\n"); }
template <int N> DINLINE void cpa_wait() { asm volatile("cp.async.wait_group %0;\n" :: "n"(N)); }

DINLINE uint32_t smem_u32(const void* p) {
    uint32_t a;
    asm("{ .reg .u64 t; cvta.to.shared.u64 t, %1; cvt.u32.u64 %0, t; }"
        : "=r"(a) : "l"(p));
    return a;
}

// ---------------------------------------------------------------------------
// Scratch
// ---------------------------------------------------------------------------
__device__ float g_Q[1048576];     // tf32-rounded bits
__device__ float g_K[1048576];     // tf32-rounded bits
__device__ float g_Vt[1048576];    // [h][d][j], tf32-rounded bits
__device__ float g_G[1048576];
__device__ float g_O[1048576];     // tf32-rounded bits (gated)
__device__ __nv_bfloat16 g_Z[16777216];  // [h][i][j] bf16
__device__ float g_R[7340032];     // tf32-rounded: s, kin, Wq, Wk, Wv, Wg, Wo

// ---------------------------------------------------------------------------
// Pre-round 7 x 1M-float buffers to tf32 (rna)
// ---------------------------------------------------------------------------
__global__ void round7_k(const float* __restrict__ s, const float* __restrict__ kin,
                         const float* __restrict__ Wq, const float* __restrict__ Wk,
                         const float* __restrict__ Wv, const float* __restrict__ Wg,
                         const float* __restrict__ Wo, float* __restrict__ R)
{
    long i = (long)blockIdx.x * 256 + threadIdx.x;   // float4 index
    int which = (int)(i >> 18);
    long off = (i & 262143) << 2;
    const float* src = which == 0 ? s : which == 1 ? kin : which == 2 ? Wq
                     : which == 3 ? Wk : which == 4 ? Wv : which == 5 ? Wg : Wo;
    float4 v = *reinterpret_cast<const float4*>(src + off);
    uint4 u = make_uint4(f2tf(v.x), f2tf(v.y), f2tf(v.z), f2tf(v.w));
    *reinterpret_cast<uint4*>(R + (long)which * 1048576 + off) = u;
}

// ---------------------------------------------------------------------------
// Pipelined tf32 GEMM core, ldmatrix fragments, NO CVT (inputs pre-rounded).
// ---------------------------------------------------------------------------
template <int BM, int BN, int WM, int WN, int TPB>
DINLINE void core_ldsm(const float* __restrict__ Ab, int lda,
                       const float* __restrict__ Bb, int ldb, int K,
                       float* sA, float* sB,
                       float (&acc)[WM / 16][WN / 8][4])
{
    constexpr int LDS = 36, BK = 32, S = 3;
    constexpr int WNC = BN / WN;
    constexpr int MT = WM / 16, NT = WN / 8, NP = NT / 2;
    const int tid = threadIdx.x, lane = tid & 31, w = tid >> 5;
    const int wn = w % WNC, wm = w / WNC;
    const int mat = lane >> 3, lr = lane & 7;

    const uint32_t sAu = smem_u32(sA), sBu = smem_u32(sB);
    const uint32_t aoff = (uint32_t)(((wm * WM + (mat & 1) * 8 + lr) * LDS
                                      + (mat >> 1) * 4) * 4);
    const uint32_t boff = (uint32_t)(((wn * WN + (mat >> 1) * 8 + lr) * LDS
                                      + (mat & 1) * 4) * 4);

    auto load_stage = [&](int tt, int st) {
        const float* Ak = Ab + tt * BK;
        const float* Bk = Bb + tt * BK;
        float* dA = sA + st * BM * LDS;
        float* dB = sB + st * BN * LDS;
#pragma unroll
        for (int idx = tid; idx < BM * 8; idx += TPB) {
            int r = idx >> 3, c = (idx & 7) << 2;
            cpa16(dA + r * LDS + c, Ak + (long)r * lda + c);
        }
#pragma unroll
        for (int idx = tid; idx < BN * 8; idx += TPB) {
            int r = idx >> 3, c = (idx & 7) << 2;
            cpa16(dB + r * LDS + c, Bk + (long)r * ldb + c);
        }
    };

    const int T = K / BK;
#pragma unroll
    for (int tt = 0; tt < S - 1; tt++) {
        if (tt < T) load_stage(tt, tt);
        cpa_commit();
    }

    for (int tt = 0; tt < T; tt++) {
        cpa_wait<S - 2>();
        __syncthreads();
        int tn = tt + S - 1;
        if (tn < T) load_stage(tn, tn % S);
        cpa_commit();

        const uint32_t aSt = sAu + (tt % S) * BM * LDS * 4;
        const uint32_t bSt = sBu + (tt % S) * BN * LDS * 4;
#pragma unroll
        for (int ks = 0; ks < 4; ks++) {
            uint32_t af[MT][4];
#pragma unroll
            for (int mt = 0; mt < MT; mt++)
                ldsm4(af[mt], aSt + aoff + mt * (16 * LDS * 4) + ks * 32);
#pragma unroll
            for (int p = 0; p < NP; p++) {
                uint32_t bf[4];
                ldsm4(bf, bSt + boff + p * (16 * LDS * 4) + ks * 32);
#pragma unroll
                for (int mt = 0; mt < MT; mt++) {
                    mma8(acc[mt][2 * p], af[mt], bf);
                    mma8(acc[mt][2 * p + 1], af[mt], bf + 2);
                }
            }
        }
    }
}

// ---------------------------------------------------------------------------
// FAT KERNEL: proj (bids 0..255) + zgemm (bids 256..4351).
// proj: 128x128 tiles, ldsm core, pre-rounded R.
// zgemm: 2 row-blocks (256 rows) per CTA through a 5-deep cp.async ring
// (~80KB in flight sustained) so the co-resident slots stream bias at high
// BW UNDER the proj phase. Output de-scattered via smem transpose.
// ---------------------------------------------------------------------------
__global__ __launch_bounds__(256, 2) void fused_pz_k(
    const float* __restrict__ R, const float* __restrict__ bq,
    const float* __restrict__ bias, const float* __restrict__ Wz,
    const float* __restrict__ mask,
    float* __restrict__ Q, float* __restrict__ Kp,
    float* __restrict__ Vt, float* __restrict__ G,
    __nv_bfloat16* __restrict__ Zout)
{
    extern __shared__ float sm[];
    const int bx = blockIdx.x;
    const int tid = threadIdx.x, lane = tid & 31, w = tid >> 5;
    const int g = lane >> 2, t4 = lane & 3;

    if (bx < 256) {
        // ---------------- proj path -------------------------------------
        float* sA = sm;
        float* sB = sm + 3 * 128 * 36;
        const int z = bx >> 6, rem = bx & 63;
        const long bm0 = (long)(rem & 7) * 128, bn0 = (long)(rem >> 3) * 128;
        const float* A = R + ((z == 0 || z == 3) ? 0L : 1L) * 1048576 + bm0 * 1024;
        const float* B = R + (long)(z + 2) * 1048576 + bn0 * 1024;

        float acc[2][8][4];
#pragma unroll
        for (int mt = 0; mt < 2; mt++)
#pragma unroll
            for (int nt = 0; nt < 8; nt++)
#pragma unroll
                for (int e = 0; e < 4; e++) acc[mt][nt][e] = 0.f;

        core_ldsm<128, 128, 32, 64, 256>(A, 1024, B, 1024, 1024, sA, sB, acc);

        const int wn = w & 1, wm = w >> 1;
#pragma unroll
        for (int mt = 0; mt < 2; mt++)
#pragma unroll
            for (int nt = 0; nt < 8; nt++)
#pragma unroll
                for (int e = 0; e < 4; e++) {
                    long m = bm0 + wm * 32 + mt * 16 + g + ((e >> 1) ? 8 : 0);
                    long n = bn0 + wn * 64 + nt * 8 + 2 * t4 + (e & 1);
                    float v = acc[mt][nt][e];
                    if (z == 0)      Q[m * 1024 + n] = __uint_as_float(f2tf(v + bq[n]));
                    else if (z == 1) Kp[m * 1024 + n] = __uint_as_float(f2tf(v));
                    else if (z == 2) Vt[n * 1024 + m] = __uint_as_float(f2tf(v));
                    else             G[m * 1024 + n] = 1.f / (1.f + expf(-v));
                }
    } else {
        // ---------------- zgemm path: Z[h, m] = bias[m,:] @ Wz[:,h] -----
        // 2 row-blocks of 128 per CTA; 8 global k-stages through 5-buffer ring
        const int bz = bx - 256;
        float* sWzT = sm;                       // [16][132]
        float* sA   = sm + 16 * 132;            // 5 x [128][36]
        __nv_bfloat16* sOut =
            (__nv_bfloat16*)(sm + 16 * 132 + 5 * 128 * 36);  // [16][136]
        const float* Ab = bias + (long)bz * 256 * 128;
        const int wm = w;

        auto issue = [&](int gs) {              // global stage gs in 0..7
            const float* Ak = Ab + (gs >> 2) * (128 * 128) + (gs & 3) * 32;
            float* dA = sA + (gs % 5) * 128 * 36;
#pragma unroll
            for (int idx = tid; idx < 1024; idx += 256) {
                int r = idx >> 3, c = (idx & 7) << 2;
                cpa16(dA + r * 36 + c, Ak + (long)r * 128 + c);
            }
        };

#pragma unroll
        for (int st = 0; st < 5; st++) { issue(st); cpa_commit(); }

        for (int idx = tid; idx < 2048; idx += 256) {
            int c = idx >> 4, hh = idx & 15;
            sWzT[hh * 132 + c] = Wz[idx];
        }

        float acc[2][4];
#pragma unroll
        for (int nt = 0; nt < 2; nt++)
#pragma unroll
            for (int e = 0; e < 4; e++) acc[nt][e] = 0.f;

#pragma unroll 1
        for (int gs = 0; gs < 8; gs++) {
            switch (gs) {
                case 0: case 1: case 2: case 3: cpa_wait<4>(); break;
                case 4: cpa_wait<3>(); break;
                case 5: cpa_wait<2>(); break;
                case 6: cpa_wait<1>(); break;
                default: cpa_wait<0>();
            }
            __syncthreads();

            const float* cA = sA + (gs % 5) * 128 * 36;
            const int tt = gs & 3;
#pragma unroll
            for (int ks = 0; ks < 4; ks++) {
                uint32_t af[4];
                af[0] = f2tf(cA[(wm * 16 + g) * 36 + ks * 8 + t4]);
                af[1] = f2tf(cA[(wm * 16 + g + 8) * 36 + ks * 8 + t4]);
                af[2] = f2tf(cA[(wm * 16 + g) * 36 + ks * 8 + t4 + 4]);
                af[3] = f2tf(cA[(wm * 16 + g + 8) * 36 + ks * 8 + t4 + 4]);
#pragma unroll
                for (int nt = 0; nt < 2; nt++) {
                    uint32_t bf[2];
                    bf[0] = f2tf(sWzT[(nt * 8 + g) * 132 + tt * 32 + ks * 8 + t4]);
                    bf[1] = f2tf(sWzT[(nt * 8 + g) * 132 + tt * 32 + ks * 8 + t4 + 4]);
                    mma8(acc[nt], af, bf);
                }
            }

            if (tt == 3) {
                // block complete: transpose via smem, coalesced bf16 writes
                const int blk = gs >> 2;
                const long mbase = (long)bz * 256 + blk * 128;
#pragma unroll
                for (int nt = 0; nt < 2; nt++)
#pragma unroll
                    for (int e = 0; e < 4; e++) {
                        int ml = wm * 16 + g + ((e >> 1) ? 8 : 0);
                        int n = nt * 8 + 2 * t4 + (e & 1);
                        float v = acc[nt][e] +
                                  (1.f - mask[(mbase + ml) & 1023]) * -1000000.f;
                        sOut[n * 136 + ml] = __float2bfloat16(v);
                        acc[nt][e] = 0.f;
                    }
                __syncthreads();
                {
                    int n = tid >> 4, chunk = tid & 15;
                    uint4 vv = *reinterpret_cast<uint4*>(&sOut[n * 136 + chunk * 8]);
                    *reinterpret_cast<uint4*>(
                        &Zout[(long)n * 1048576 + mbase + chunk * 8]) = vv;
                }
            }
            __syncthreads();
            if (gs + 5 < 8) { issue(gs + 5); cpa_commit(); }
        }
    }
}

// ---------------------------------------------------------------------------
// Final projection: out = O_gated @ Wo^T  (both pre-rounded -> ldsm core)
// ---------------------------------------------------------------------------
__global__ __launch_bounds__(256) void fgemm_k(
    const float* __restrict__ A, const float* __restrict__ B,
    float* __restrict__ C)
{
    extern __shared__ float sm[];
    float* sA = sm;
    float* sB = sm + 3 * 64 * 36;

    const long bm0 = (long)blockIdx.x * 64, bn0 = (long)blockIdx.y * 64;
    float acc[1][4][4];
#pragma unroll
    for (int nt = 0; nt < 4; nt++)
#pragma unroll
        for (int e = 0; e < 4; e++) acc[0][nt][e] = 0.f;

    core_ldsm<64, 64, 16, 32, 256>(A + bm0 * 1024, 1024, B + bn0 * 1024, 1024,
                                   1024, sA, sB, acc);

    const int tid = threadIdx.x, lane = tid & 31, w = tid >> 5;
    const int g = lane >> 2, t4 = lane & 3;
    const int wn = w & 1, wm = w >> 1;
#pragma unroll
    for (int nt = 0; nt < 4; nt++)
#pragma unroll
        for (int e = 0; e < 4; e++) {
            long m = bm0 + wm * 16 + g + ((e >> 1) ? 8 : 0);
            long n = bn0 + wn * 32 + nt * 8 + 2 * t4 + (e & 1);
            C[m * 1024 + n] = acc[0][nt][e];
        }
}

// ---------------------------------------------------------------------------
// Flash attention per (i-tile 64, head). Pre-rounded tf32 operands, ldmatrix
// fragments. Z read DIRECTLY to registers (used once; no smem staging).
// ---------------------------------------------------------------------------
#define FT 4352                     // 64*68 floats
__global__ __launch_bounds__(128) void flash_k(
    const float* __restrict__ Q, const float* __restrict__ K,
    const float* __restrict__ Vt, const __nv_bfloat16* __restrict__ Z,
    const float* __restrict__ G, float* __restrict__ O)
{
    extern __shared__ float sm[];
    const uint32_t smu = smem_u32(sm);
    const int h = blockIdx.y;
    const long i0 = (long)blockIdx.x * 64;
    const int tid = threadIdx.x, w = tid >> 5, lane = tid & 31;
    const int g = lane >> 2, t4 = lane & 3;
    const int r0 = w * 16 + g;
    const int mat = lane >> 3, lr = lane & 7;
    const uint32_t bfr = (uint32_t)((((mat >> 1) * 8 + lr) * 68 + (mat & 1) * 4) * 4);
    const uint32_t afr = (uint32_t)(((w * 16 + (mat & 1) * 8 + lr) * 68
                                     + (mat >> 1) * 4) * 4);

    uint32_t qa[8][4];
    {
        const uint32_t* Qb = (const uint32_t*)(Q + i0 * 1024 + h * 64);
#pragma unroll
        for (int ks = 0; ks < 8; ks++) {
            qa[ks][0] = Qb[(long)r0 * 1024 + ks * 8 + t4];
            qa[ks][1] = Qb[(long)(r0 + 8) * 1024 + ks * 8 + t4];
            qa[ks][2] = Qb[(long)r0 * 1024 + ks * 8 + t4 + 4];
            qa[ks][3] = Qb[(long)(r0 + 8) * 1024 + ks * 8 + t4 + 4];
        }
    }

    float oacc[8][4];
#pragma unroll
    for (int nt = 0; nt < 8; nt++)
#pragma unroll
        for (int e = 0; e < 4; e++) oacc[nt][e] = 0.f;
    float m0 = -1e30f, m1 = -1e30f, l0 = 0.f, l1 = 0.f;

    // Z row bases for this thread (rows i0+r0 and i0+r0+8)
    const __nv_bfloat16* Zr0 = Z + (long)h * 1048576 + (i0 + r0) * 1024 + 2 * t4;
    const __nv_bfloat16* Zr1 = Zr0 + 8 * 1024;

    auto stage = [&](int jt, int b) {
        const float* Ksrc = K + (long)jt * 64 * 1024 + h * 64;
        const float* Vsrc = Vt + (long)h * 65536 + jt * 64;
        float* dK = sm + b * FT;
        float* dV = sm + (2 + b) * FT;
#pragma unroll
        for (int idx = tid; idx < 1024; idx += 128) {
            int r = idx >> 4, c = (idx & 15) << 2;
            cpa16(dK + r * 68 + c, Ksrc + (long)r * 1024 + c);
            cpa16(dV + r * 68 + c, Vsrc + (long)r * 1024 + c);
        }
    };

    stage(0, 0);
    cpa_commit();

    for (int jt = 0; jt < 16; jt++) {
        const int b = jt & 1;

        // issue Z loads for this tile early (registers; hidden under QK mma)
        __nv_bfloat162 zr0[8], zr1[8];
#pragma unroll
        for (int nt = 0; nt < 8; nt++) {
            zr0[nt] = *reinterpret_cast<const __nv_bfloat162*>(&Zr0[jt * 64 + nt * 8]);
            zr1[nt] = *reinterpret_cast<const __nv_bfloat162*>(&Zr1[jt * 64 + nt * 8]);
        }

        cpa_wait<0>();
        __syncthreads();
        if (jt < 15) { stage(jt + 1, b ^ 1); cpa_commit(); }

        const uint32_t kbu = smu + b * FT * 4;
        const uint32_t vbu = smu + (2 + b) * FT * 4;

        float sacc[8][4];
#pragma unroll
        for (int nt = 0; nt < 8; nt++)
#pragma unroll
            for (int e = 0; e < 4; e++) sacc[nt][e] = 0.f;
#pragma unroll
        for (int ks = 0; ks < 8; ks++) {
#pragma unroll
            for (int p = 0; p < 4; p++) {
                uint32_t bk[4];
                ldsm4(bk, kbu + bfr + p * (16 * 68 * 4) + ks * 32);
                mma8(sacc[2 * p], qa[ks], bk);
                mma8(sacc[2 * p + 1], qa[ks], bk + 2);
            }
        }

#pragma unroll
        for (int nt = 0; nt < 8; nt++) {
            const float2 z0 = __bfloat1622float2(zr0[nt]);
            const float2 z1 = __bfloat1622float2(zr1[nt]);
            sacc[nt][0] = fmaf(sacc[nt][0], 0.125f, z0.x);
            sacc[nt][1] = fmaf(sacc[nt][1], 0.125f, z0.y);
            sacc[nt][2] = fmaf(sacc[nt][2], 0.125f, z1.x);
            sacc[nt][3] = fmaf(sacc[nt][3], 0.125f, z1.y);
        }

        float mx0 = -1e30f, mx1 = -1e30f;
#pragma unroll
        for (int nt = 0; nt < 8; nt++) {
            mx0 = fmaxf(mx0, fmaxf(sacc[nt][0], sacc[nt][1]));
            mx1 = fmaxf(mx1, fmaxf(sacc[nt][2], sacc[nt][3]));
        }
        mx0 = fmaxf(mx0, __shfl_xor_sync(0xFFFFFFFFu, mx0, 1));
        mx0 = fmaxf(mx0, __shfl_xor_sync(0xFFFFFFFFu, mx0, 2));
        mx1 = fmaxf(mx1, __shfl_xor_sync(0xFFFFFFFFu, mx1, 1));
        mx1 = fmaxf(mx1, __shfl_xor_sync(0xFFFFFFFFu, mx1, 2));

        const float mn0 = fmaxf(m0, mx0), mn1 = fmaxf(m1, mx1);
        const float a0 = __expf(m0 - mn0), a1 = __expf(m1 - mn1);
        m0 = mn0; m1 = mn1;

        float rs0 = 0.f, rs1 = 0.f;
#pragma unroll
        for (int nt = 0; nt < 8; nt++) {
            sacc[nt][0] = __expf(sacc[nt][0] - mn0);
            sacc[nt][1] = __expf(sacc[nt][1] - mn0);
            sacc[nt][2] = __expf(sacc[nt][2] - mn1);
            sacc[nt][3] = __expf(sacc[nt][3] - mn1);
            rs0 += sacc[nt][0] + sacc[nt][1];
            rs1 += sacc[nt][2] + sacc[nt][3];
        }
        rs0 += __shfl_xor_sync(0xFFFFFFFFu, rs0, 1);
        rs0 += __shfl_xor_sync(0xFFFFFFFFu, rs0, 2);
        rs1 += __shfl_xor_sync(0xFFFFFFFFu, rs1, 1);
        rs1 += __shfl_xor_sync(0xFFFFFFFFu, rs1, 2);
        l0 = l0 * a0 + rs0;
        l1 = l1 * a1 + rs1;
#pragma unroll
        for (int nt = 0; nt < 8; nt++) {
            oacc[nt][0] *= a0; oacc[nt][1] *= a0;
            oacc[nt][2] *= a1; oacc[nt][3] *= a1;
        }

        __syncthreads();
        uint32_t* pP = (uint32_t*)(sm + b * FT);
#pragma unroll
        for (int nt = 0; nt < 8; nt++) {
            uint2 p0 = make_uint2(f2tf(sacc[nt][0]), f2tf(sacc[nt][1]));
            uint2 p1 = make_uint2(f2tf(sacc[nt][2]), f2tf(sacc[nt][3]));
            *reinterpret_cast<uint2*>(&pP[r0 * 68 + nt * 8 + 2 * t4]) = p0;
            *reinterpret_cast<uint2*>(&pP[(r0 + 8) * 68 + nt * 8 + 2 * t4]) = p1;
        }
        __syncwarp();

#pragma unroll
        for (int ks = 0; ks < 8; ks++) {
            uint32_t pa[4];
            ldsm4(pa, kbu + afr + ks * 32);
#pragma unroll
            for (int p = 0; p < 4; p++) {
                uint32_t bv[4];
                ldsm4(bv, vbu + bfr + p * (16 * 68 * 4) + ks * 32);
                mma8(oacc[2 * p], pa, bv);
                mma8(oacc[2 * p + 1], pa, bv + 2);
            }
        }
    }

    const float iv0 = 1.f / l0, iv1 = 1.f / l1;
#pragma unroll
    for (int nt = 0; nt < 8; nt++) {
        const int c = h * 64 + nt * 8 + 2 * t4;
        const long ro0 = (i0 + r0) * 1024 + c;
        const long ro1 = (i0 + r0 + 8) * 1024 + c;
        const float2 g0 = *reinterpret_cast<const float2*>(&G[ro0]);
        const float2 g1 = *reinterpret_cast<const float2*>(&G[ro1]);
        *reinterpret_cast<uint2*>(&O[ro0]) =
            make_uint2(f2tf(oacc[nt][0] * iv0 * g0.x), f2tf(oacc[nt][1] * iv0 * g0.y));
        *reinterpret_cast<uint2*>(&O[ro1]) =
            make_uint2(f2tf(oacc[nt][2] * iv1 * g1.x), f2tf(oacc[nt][3] * iv1 * g1.y));
    }
}

// ---------------------------------------------------------------------------
// Launch
// ---------------------------------------------------------------------------
extern "C" void kernel_launch(void* const* d_in, const int* in_sizes, int n_in,
                              void* d_out, int out_size)
{
    const float* s    = (const float*)d_in[0];
    const float* k_in = (const float*)d_in[1];
    const float* mask = (const float*)d_in[2];
    const float* bias = (const float*)d_in[3];
    const float* Wq   = (const float*)d_in[4];
    const float* bq   = (const float*)d_in[5];
    const float* Wk   = (const float*)d_in[6];
    const float* Wv   = (const float*)d_in[7];
    const float* Wg   = (const float*)d_in[8];
    const float* Wo   = (const float*)d_in[9];
    const float* Wz   = (const float*)d_in[10];
    float* out = (float*)d_out;

    float *Q, *Kp, *Vt, *G, *O, *R;
    __nv_bfloat16* Z;
    cudaGetSymbolAddress((void**)&Q,  g_Q);
    cudaGetSymbolAddress((void**)&Kp, g_K);
    cudaGetSymbolAddress((void**)&Vt, g_Vt);
    cudaGetSymbolAddress((void**)&G,  g_G);
    cudaGetSymbolAddress((void**)&O,  g_O);
    cudaGetSymbolAddress((void**)&Z,  g_Z);
    cudaGetSymbolAddress((void**)&R,  g_R);

    const int SM_FAT   = 3 * (128 + 128) * 36 * 4;       // 110592
    const int SM_6464  = 3 * (64 + 64) * 36 * 4;         //  55296
    const int SM_FLASH = 4 * FT * 4;                     //  69632

    cudaFuncSetAttribute((const void*)fused_pz_k,
                         cudaFuncAttributeMaxDynamicSharedMemorySize, SM_FAT);
    cudaFuncSetAttribute((const void*)fgemm_k,
                         cudaFuncAttributeMaxDynamicSharedMemorySize, SM_6464);
    cudaFuncSetAttribute((const void*)flash_k,
                         cudaFuncAttributeMaxDynamicSharedMemorySize, SM_FLASH);

    // pre-round s, kin, Wq, Wk, Wv, Wg, Wo to tf32 (rna)
    round7_k<<<7168, 256>>>(s, k_in, Wq, Wk, Wv, Wg, Wo, R);

    // proj (256 CTAs) + zgemm (4096 long-lived streaming CTAs) overlapped
    fused_pz_k<<<4352, 256, SM_FAT>>>(R, bq, bias, Wz, mask, Q, Kp, Vt, G, Z);

    // fused attention + gating (Z direct from DRAM, no smem staging)
    flash_k<<<dim3(16, 16), 128, SM_FLASH>>>(Q, Kp, Vt, Z, G, O);

    // out = O_gated @ Wo^T — ldsm core, no CVT
    fgemm_k<<<dim3(16, 16), 256, SM_6464>>>(O, R + 6 * 1048576, out);
}